// round 15
// baseline (speedup 1.0000x reference)
#include <cuda_runtime.h>
#include <math.h>
#include <stdint.h>

// ---------------------------------------------------------------------------
// PatchAttentionNet: B=4, N=256, O=5, K=5, F=256, H=4, D=64, DFF=1024
// R1:  algebraic refactor (center-q => no k/v projections)
// R2/3: TF32 tensor-core GEMMs, pre-converted operands, ldmatrix
// R6:  LN partial sums fused into GEMM epilogues
// R8:  qc fp32 path deleted (cterm via wbk/cbk); smem-staged attn
// R11/12: all GEMMs 64x64; attn at default occupancy
// R14: out1 fp32 dropped (tf32 residual); float4 LN  (168.7us)
// R15: W1 on a 128x64-tile kernel (640 CTAs; halves W1 L2 traffic while
//      keeping multi-wave CTA count)
// ---------------------------------------------------------------------------

#define BATCH 4
#define NPOS 256
#define OPOS 5
#define FDIM 256
#define HHEADS 4
#define DHEAD 64
#define DFFDIM 1024
#define SITES (BATCH*NPOS*OPOS)     // 5120
#define PATCHES 25
#define PERBATCH (NPOS*OPOS*FDIM)   // 327680
#define TOTAL (BATCH*PERBATCH)      // 1310720
#define EPSV 1e-5f
#define NPART 80                    // LN partials per batch (20 rowblk x 4 colblk)

// ---- scratch (device globals; allocation-free) ----
__device__ uint32_t g_xc[SITES*FDIM];
__device__ uint32_t g_wq[FDIM*FDIM];
__device__ uint32_t g_wkT[HHEADS*FDIM*DHEAD];
__device__ uint32_t g_wv[HHEADS*DHEAD*FDIM];
__device__ uint32_t g_wf[FDIM*FDIM];
__device__ uint32_t g_w1[DFFDIM*FDIM];
__device__ uint32_t g_w2[FDIM*DFFDIM];
__device__ float    g_wbk[HHEADS*FDIM];   // Wq_h^T bk_h
__device__ float    g_cbk[HHEADS];        // bq_h . bk_h
__device__ uint32_t g_qctf[SITES*FDIM];
__device__ float    g_u[SITES*HHEADS*FDIM];
__device__ uint32_t g_xbtf[SITES*HHEADS*FDIM];
__device__ uint32_t g_mgtf[SITES*FDIM];
__device__ float    g_attent[SITES*FDIM];
__device__ uint32_t g_out1tf[SITES*FDIM];
__device__ uint32_t g_hidtf[SITES*DFFDIM];
__device__ float    g_t[SITES*FDIM];
__device__ float    g_part[2*BATCH*NPART];

__device__ __forceinline__ uint32_t f2tf(float v) {
    uint32_t r;
    asm("cvt.rna.tf32.f32 %0, %1;" : "=r"(r) : "f"(v));
    return r;
}

__device__ __forceinline__ void mma_tf32(float c[4], const uint32_t a[4],
                                         uint32_t b0, uint32_t b1) {
    asm volatile(
        "mma.sync.aligned.m16n8k8.row.col.f32.tf32.tf32.f32 "
        "{%0,%1,%2,%3},{%4,%5,%6,%7},{%8,%9},{%0,%1,%2,%3};"
        : "+f"(c[0]), "+f"(c[1]), "+f"(c[2]), "+f"(c[3])
        : "r"(a[0]), "r"(a[1]), "r"(a[2]), "r"(a[3]), "r"(b0), "r"(b1));
}

__device__ __forceinline__ void ldsm4(uint32_t r[4], uint32_t addr) {
    asm volatile("ldmatrix.sync.aligned.m8n8.x4.shared.b16 {%0,%1,%2,%3}, [%4];"
                 : "=r"(r[0]), "=r"(r[1]), "=r"(r[2]), "=r"(r[3]) : "r"(addr));
}

__device__ __forceinline__ void cpa16(uint32_t dst, const void* src) {
    asm volatile("cp.async.cg.shared.global [%0], [%1], 16;" :: "r"(dst), "l"(src));
}

// ---------------------------------------------------------------------------
// One-shot tf32 conversion + cterm precompute (wbk, cbk)
// ---------------------------------------------------------------------------
__global__ void convert_tf(const float* __restrict__ Wq, const float* __restrict__ Wk,
                           const float* __restrict__ Wv, const float* __restrict__ Wf,
                           const float* __restrict__ W1, const float* __restrict__ W2,
                           const float* __restrict__ x,
                           const float* __restrict__ bq, const float* __restrict__ bk)
{
    const int idx = blockIdx.x * 256 + threadIdx.x;
    if (idx < 65536) {
        g_wq[idx] = f2tf(Wq[idx]);
    } else if (idx < 131072) {
        const int i = idx - 65536;
        const int h = i >> 14, n = (i >> 6) & 255, k = i & 63;
        g_wkT[i] = f2tf(Wk[(h*64 + k)*256 + n]);
    } else if (idx < 196608) {
        const int i = idx - 131072;
        g_wv[i] = f2tf(Wv[i]);
    } else if (idx < 262144) {
        const int i = idx - 196608;
        g_wf[i] = f2tf(Wf[i]);
    } else if (idx < 524288) {
        const int i = idx - 262144;
        g_w1[i] = f2tf(W1[i]);
    } else if (idx < 786432) {
        const int i = idx - 524288;
        g_w2[i] = f2tf(W2[i]);
    } else if (idx < 2097152) {
        const int i = idx - 786432;
        const int s = i >> 8, f = i & 255;
        g_xc[i] = f2tf(x[(long)s*(PATCHES*FDIM) + 12*FDIM + f]);
    } else if (idx < 2098176) {
        const int i = idx - 2097152;        // wbk[h][f] = sum_d Wq[h*64+d][f]*bk[h*64+d]
        const int h = i >> 8, f = i & 255;
        float a = 0.f;
#pragma unroll 8
        for (int d = 0; d < 64; d++)
            a += Wq[(h*64 + d)*256 + f] * bk[h*64 + d];
        g_wbk[i] = a;
    } else if (idx < 2098180) {
        const int h = idx - 2098176;        // cbk[h] = bq_h . bk_h
        float a = 0.f;
#pragma unroll 8
        for (int d = 0; d < 64; d++)
            a += bq[h*64 + d] * bk[h*64 + d];
        g_cbk[h] = a;
    }
}

// ---------------------------------------------------------------------------
// 64x64x32 TF32 GEMM: C[M,N] = A[M,K] @ B^T (+bias)(+tf32-res)(relu)(+LN part)
// ---------------------------------------------------------------------------
#define BMT 64
#define BNT 64
#define BKT 32
#define PADA 36
#define PADB 36
#define ABUF (BMT*PADA)
#define BBUF (BNT*PADB)
#define SPB  (ABUF+BBUF)

template<bool RELU, bool HASRES, bool HASBIAS, bool WRF32, bool WRTF, bool LNPART>
__global__ void __launch_bounds__(128)
mm_tc(const uint32_t* __restrict__ A, int lda, int sAz,
      const uint32_t* __restrict__ B, int ldb, int sBz,
      float* __restrict__ C, uint32_t* __restrict__ Ctf, int ldc, int sCz,
      const float* __restrict__ bias, int sBiasz,
      const uint32_t* __restrict__ res, int K,
      float* __restrict__ part)
{
    __shared__ uint32_t sm[2*SPB];
    const int z = blockIdx.z;
    A += (long)z * sAz;
    B += (long)z * sBz;
    const long coff_z = (long)z * sCz;
    const float* biasz = HASBIAS ? bias + (long)z * sBiasz : bias;

    const int m0 = blockIdx.y * BMT;
    const int n0 = blockIdx.x * BNT;
    const int tid = threadIdx.x;
    const int warp = tid >> 5, lane = tid & 31;
    const int g = lane >> 2, tig = lane & 3;
    const int wm = warp >> 1, wn = warp & 1;

    const uint32_t uS = (uint32_t)__cvta_generic_to_shared(sm);
    const uint32_t aoff = (uint32_t)(((wm*32 + (lane & 15)) * PADA + ((lane >> 4) << 2)) * 4);
    const uint32_t boff = (uint32_t)((ABUF + (wn*32 + (lane & 15)) * PADB + ((lane >> 4) << 2)) * 4);

    float c[2][4][4];
#pragma unroll
    for (int mf = 0; mf < 2; mf++)
#pragma unroll
        for (int nf = 0; nf < 4; nf++)
#pragma unroll
            for (int i = 0; i < 4; i++) c[mf][nf][i] = 0.f;

    const int nslab = K / BKT;

    auto load_slab = [&](int ks, int buf) {
        const uint32_t base = uS + (uint32_t)(buf * SPB * 4);
        const uint32_t* Ag = A + (long)m0 * lda + ks * BKT;
        const uint32_t* Bg = B + (long)n0 * ldb + ks * BKT;
#pragma unroll
        for (int i = 0; i < 4; i++) {
            int id = tid + i * 128;
            int r = id >> 3;
            int kc4 = (id & 7) * 4;
            cpa16(base + (uint32_t)((r * PADA + kc4) * 4), Ag + (long)r * lda + kc4);
        }
#pragma unroll
        for (int i = 0; i < 4; i++) {
            int id = tid + i * 128;
            int r = id >> 3;
            int kc4 = (id & 7) * 4;
            cpa16(base + (uint32_t)((ABUF + r * PADB + kc4) * 4), Bg + (long)r * ldb + kc4);
        }
        asm volatile("cp.async.commit_group;");
    };

    load_slab(0, 0);

    for (int ks = 0; ks < nslab; ks++) {
        const int cur = ks & 1;
        if (ks + 1 < nslab) {
            load_slab(ks + 1, cur ^ 1);
            asm volatile("cp.async.wait_group 1;");
        } else {
            asm volatile("cp.async.wait_group 0;");
        }
        __syncthreads();

        const uint32_t sb = uS + (uint32_t)(cur * SPB * 4);
        const uint32_t aaddr = sb + aoff;
        const uint32_t baddr = sb + boff;

#pragma unroll
        for (int kc = 0; kc < BKT; kc += 8) {
            uint32_t a0[4], a1[4], b01[4], b23[4];
            ldsm4(a0, aaddr + kc * 4);
            ldsm4(a1, aaddr + (16 * PADA + kc) * 4);
            ldsm4(b01, baddr + kc * 4);
            ldsm4(b23, baddr + (16 * PADB + kc) * 4);
            mma_tf32(c[0][0], a0, b01[0], b01[2]);
            mma_tf32(c[0][1], a0, b01[1], b01[3]);
            mma_tf32(c[0][2], a0, b23[0], b23[2]);
            mma_tf32(c[0][3], a0, b23[1], b23[3]);
            mma_tf32(c[1][0], a1, b01[0], b01[2]);
            mma_tf32(c[1][1], a1, b01[1], b01[3]);
            mma_tf32(c[1][2], a1, b23[0], b23[2]);
            mma_tf32(c[1][3], a1, b23[1], b23[3]);
        }
        __syncthreads();
    }

    float ls = 0.f, lss = 0.f;
#pragma unroll
    for (int mf = 0; mf < 2; mf++) {
        const int r0 = m0 + wm*32 + mf*16 + g;
#pragma unroll
        for (int nf = 0; nf < 4; nf++) {
            const int col = n0 + wn*32 + nf*8 + 2*tig;
            float bx = 0.f, by = 0.f;
            if (HASBIAS) {
                float2 bb = *(const float2*)&biasz[col];
                bx = bb.x; by = bb.y;
            }
            float v0 = c[mf][nf][0] + bx, v1 = c[mf][nf][1] + by;
            float v2 = c[mf][nf][2] + bx, v3 = c[mf][nf][3] + by;
            if (RELU) {
                v0 = fmaxf(v0, 0.f); v1 = fmaxf(v1, 0.f);
                v2 = fmaxf(v2, 0.f); v3 = fmaxf(v3, 0.f);
            }
            if (HASRES) {
                uint2 ra = *(const uint2*)&res[(long)r0 * ldc + coff_z + col];
                uint2 rb = *(const uint2*)&res[(long)(r0 + 8) * ldc + coff_z + col];
                v0 += __uint_as_float(ra.x); v1 += __uint_as_float(ra.y);
                v2 += __uint_as_float(rb.x); v3 += __uint_as_float(rb.y);
            }
            if (LNPART) {
                ls  += (v0 + v1) + (v2 + v3);
                lss += (v0*v0 + v1*v1) + (v2*v2 + v3*v3);
            }
            if (WRF32) {
                float2 o0; o0.x = v0; o0.y = v1;
                float2 o1; o1.x = v2; o1.y = v3;
                *(float2*)&C[(long)r0 * ldc + coff_z + col] = o0;
                *(float2*)&C[(long)(r0 + 8) * ldc + coff_z + col] = o1;
            }
            if (WRTF) {
                uint2 t0; t0.x = f2tf(v0); t0.y = f2tf(v1);
                uint2 t1; t1.x = f2tf(v2); t1.y = f2tf(v3);
                *(uint2*)&Ctf[(long)r0 * ldc + coff_z + col] = t0;
                *(uint2*)&Ctf[(long)(r0 + 8) * ldc + coff_z + col] = t1;
            }
        }
    }

    if (LNPART) {
        __shared__ float red[2][4];
#pragma unroll
        for (int o = 16; o; o >>= 1) {
            ls  += __shfl_xor_sync(0xffffffffu, ls, o);
            lss += __shfl_xor_sync(0xffffffffu, lss, o);
        }
        if (lane == 0) { red[0][warp] = ls; red[1][warp] = lss; }
        __syncthreads();
        if (tid == 0) {
            float S = (red[0][0] + red[0][1]) + (red[0][2] + red[0][3]);
            float SS = (red[1][0] + red[1][1]) + (red[1][2] + red[1][3]);
            const int b = blockIdx.y / 20;
            const int idx = b * NPART + (blockIdx.y % 20) * 4 + blockIdx.x;
            part[idx] = S;
            part[BATCH*NPART + idx] = SS;
        }
    }
}

// ---------------------------------------------------------------------------
// 128x64x32 TF32 GEMM for W1 (relu + bias + tf32 out). 128 threads, 4 warps,
// warp tile 32x64 (6 ldsm : 16 mma). Dynamic smem 55.3KB. grid (16,40)=640.
// ---------------------------------------------------------------------------
#define WBM 128
#define ABUFW (WBM*PADA)            // 4608 u32
#define SPBW (ABUFW + BBUF)         // 6912 u32
#define SMEMW (2*SPBW*4)            // 55296 B

__global__ void __launch_bounds__(128)
mm_tcw(const uint32_t* __restrict__ A, int lda,
       const uint32_t* __restrict__ B, int ldb,
       uint32_t* __restrict__ Ctf, int ldc,
       const float* __restrict__ bias, int K)
{
    extern __shared__ uint32_t smw[];
    const int m0 = blockIdx.y * WBM;
    const int n0 = blockIdx.x * BNT;
    const int tid = threadIdx.x;
    const int warp = tid >> 5, lane = tid & 31;
    const int g = lane >> 2, tig = lane & 3;

    const uint32_t uS = (uint32_t)__cvta_generic_to_shared(smw);
    const uint32_t aoff = (uint32_t)(((warp*32 + (lane & 15)) * PADA + ((lane >> 4) << 2)) * 4);
    const uint32_t boff = (uint32_t)((ABUFW + (lane & 15) * PADB + ((lane >> 4) << 2)) * 4);

    float c[2][8][4];
#pragma unroll
    for (int mf = 0; mf < 2; mf++)
#pragma unroll
        for (int nf = 0; nf < 8; nf++)
#pragma unroll
            for (int i = 0; i < 4; i++) c[mf][nf][i] = 0.f;

    const int nslab = K / BKT;

    auto load_slab = [&](int ks, int buf) {
        const uint32_t base = uS + (uint32_t)(buf * SPBW * 4);
        const uint32_t* Ag = A + (long)m0 * lda + ks * BKT;
        const uint32_t* Bg = B + (long)n0 * ldb + ks * BKT;
#pragma unroll
        for (int i = 0; i < 8; i++) {          // 128 rows x 8 float4
            int id = tid + i * 128;
            int r = id >> 3;
            int kc4 = (id & 7) * 4;
            cpa16(base + (uint32_t)((r * PADA + kc4) * 4), Ag + (long)r * lda + kc4);
        }
#pragma unroll
        for (int i = 0; i < 4; i++) {          // 64 rows x 8 float4
            int id = tid + i * 128;
            int r = id >> 3;
            int kc4 = (id & 7) * 4;
            cpa16(base + (uint32_t)((ABUFW + r * PADB + kc4) * 4), Bg + (long)r * ldb + kc4);
        }
        asm volatile("cp.async.commit_group;");
    };

    load_slab(0, 0);

    for (int ks = 0; ks < nslab; ks++) {
        const int cur = ks & 1;
        if (ks + 1 < nslab) {
            load_slab(ks + 1, cur ^ 1);
            asm volatile("cp.async.wait_group 1;");
        } else {
            asm volatile("cp.async.wait_group 0;");
        }
        __syncthreads();

        const uint32_t sb = uS + (uint32_t)(cur * SPBW * 4);
        const uint32_t aaddr = sb + aoff;
        const uint32_t baddr = sb + boff;

#pragma unroll
        for (int kc = 0; kc < BKT; kc += 8) {
            uint32_t a0[4], a1[4], b[4][4];
            ldsm4(a0, aaddr + kc * 4);
            ldsm4(a1, aaddr + (16 * PADA + kc) * 4);
#pragma unroll
            for (int nb = 0; nb < 4; nb++)
                ldsm4(b[nb], baddr + (nb * 16 * PADB + kc) * 4);
#pragma unroll
            for (int nb = 0; nb < 4; nb++) {
                mma_tf32(c[0][2*nb+0], a0, b[nb][0], b[nb][2]);
                mma_tf32(c[0][2*nb+1], a0, b[nb][1], b[nb][3]);
                mma_tf32(c[1][2*nb+0], a1, b[nb][0], b[nb][2]);
                mma_tf32(c[1][2*nb+1], a1, b[nb][1], b[nb][3]);
            }
        }
        __syncthreads();
    }

#pragma unroll
    for (int mf = 0; mf < 2; mf++) {
        const int r0 = m0 + warp*32 + mf*16 + g;
#pragma unroll
        for (int nf = 0; nf < 8; nf++) {
            const int col = n0 + nf*8 + 2*tig;
            float2 bb = *(const float2*)&bias[col];
            float v0 = fmaxf(c[mf][nf][0] + bb.x, 0.f);
            float v1 = fmaxf(c[mf][nf][1] + bb.y, 0.f);
            float v2 = fmaxf(c[mf][nf][2] + bb.x, 0.f);
            float v3 = fmaxf(c[mf][nf][3] + bb.y, 0.f);
            uint2 t0; t0.x = f2tf(v0); t0.y = f2tf(v1);
            uint2 t1; t1.x = f2tf(v2); t1.y = f2tf(v3);
            *(uint2*)&Ctf[(long)r0 * ldc + col] = t0;
            *(uint2*)&Ctf[(long)(r0 + 8) * ldc + col] = t1;
        }
    }
}

// ---------------------------------------------------------------------------
// Attention: smem-staged X/u, cterm from sX[12].wbk + cbk. (measured optimum)
// ---------------------------------------------------------------------------
__global__ void __launch_bounds__(256) attn_kernel(
    const float* __restrict__ x,
    const float* __restrict__ u,
    const float* __restrict__ wbk, const float* __restrict__ cbk,
    uint32_t* __restrict__ xbar_tf)
{
    __shared__ float sX[PATCHES * FDIM];
    __shared__ float sU[HHEADS * FDIM];
    __shared__ float sct[HHEADS];
    __shared__ float sSc[HHEADS * PATCHES];
    __shared__ float sWp[PATCHES * 4];

    const int s = blockIdx.x;
    const int tid = threadIdx.x;
    const int warp = tid >> 5, lane = tid & 31;

    const uint32_t uX = (uint32_t)__cvta_generic_to_shared(sX);
    const uint32_t uU = (uint32_t)__cvta_generic_to_shared(sU);
    const float* xg = x + (long)s * (PATCHES * FDIM);
    for (int i = tid; i < PATCHES * FDIM / 4; i += 256)
        cpa16(uX + (uint32_t)i * 16, xg + i * 4);
    cpa16(uU + (uint32_t)tid * 16, u + (long)s * (HHEADS * FDIM) + tid * 4);
    asm volatile("cp.async.commit_group;");
    asm volatile("cp.async.wait_group 0;");
    __syncthreads();

    if (warp < HHEADS) {
        float v = 0.f;
#pragma unroll
        for (int j = 0; j < 8; j++)
            v += sX[12*FDIM + lane + 32*j] * wbk[warp*FDIM + lane + 32*j];
#pragma unroll
        for (int o = 16; o; o >>= 1) v += __shfl_xor_sync(0xffffffffu, v, o);
        if (lane == 0) sct[warp] = v + cbk[warp];
    }

    float4 ua[HHEADS], ub[HHEADS];
#pragma unroll
    for (int h = 0; h < HHEADS; h++) {
        ua[h] = ((const float4*)&sU[h * FDIM])[lane];
        ub[h] = ((const float4*)&sU[h * FDIM])[lane + 32];
    }
    __syncthreads();

    for (int p = warp; p < PATCHES; p += 8) {
        const float4 xa = ((const float4*)&sX[p * FDIM])[lane];
        const float4 xb = ((const float4*)&sX[p * FDIM])[lane + 32];
        float acc[HHEADS];
#pragma unroll
        for (int h = 0; h < HHEADS; h++) {
            acc[h] = xa.x*ua[h].x + xa.y*ua[h].y + xa.z*ua[h].z + xa.w*ua[h].w
                   + xb.x*ub[h].x + xb.y*ub[h].y + xb.z*ub[h].z + xb.w*ub[h].w;
        }
#pragma unroll
        for (int o = 16; o; o >>= 1) {
#pragma unroll
            for (int h = 0; h < HHEADS; h++)
                acc[h] += __shfl_xor_sync(0xffffffffu, acc[h], o);
        }
        if (lane == 0) {
#pragma unroll
            for (int h = 0; h < HHEADS; h++)
                sSc[h * PATCHES + p] = (acc[h] + sct[h]) * 0.125f;
        }
    }
    __syncthreads();

    if (warp < HHEADS) {
        float v = (lane < PATCHES) ? sSc[warp * PATCHES + lane] : -1e30f;
        float m = v;
#pragma unroll
        for (int o = 16; o; o >>= 1) m = fmaxf(m, __shfl_xor_sync(0xffffffffu, m, o));
        float e = (lane < PATCHES) ? __expf(v - m) : 0.f;
        float sum = e;
#pragma unroll
        for (int o = 16; o; o >>= 1) sum += __shfl_xor_sync(0xffffffffu, sum, o);
        if (lane < PATCHES) sWp[lane * 4 + warp] = e / sum;
    }
    __syncthreads();

    float acc0 = 0.f, acc1 = 0.f, acc2 = 0.f, acc3 = 0.f;
#pragma unroll
    for (int p = 0; p < PATCHES; p++) {
        const float xv = sX[p * FDIM + tid];
        const float4 wv = *(const float4*)&sWp[p * 4];
        acc0 += wv.x * xv; acc1 += wv.y * xv;
        acc2 += wv.z * xv; acc3 += wv.w * xv;
    }
    uint32_t* xo = xbar_tf + (long)s * (HHEADS * FDIM) + tid;
    xo[0*FDIM] = f2tf(acc0);
    xo[1*FDIM] = f2tf(acc1);
    xo[2*FDIM] = f2tf(acc2);
    xo[3*FDIM] = f2tf(acc3);
}

// ---------------------------------------------------------------------------
// LN apply (float4-vectorized)
// ---------------------------------------------------------------------------
template<bool WRF32, bool WRTF>
__global__ void ln_apply(const float4* __restrict__ in4, const float* __restrict__ part,
                         const float4* __restrict__ w4, const float4* __restrict__ b4,
                         float4* __restrict__ out4, uint4* __restrict__ out_tf4)
{
    __shared__ float s_mu, s_rs;
    const int idx = blockIdx.x * 256 + threadIdx.x;
    const int b = blockIdx.x / (PERBATCH / 1024);
    if (threadIdx.x < 32) {
        float s = 0.f, ss = 0.f;
        for (int i = threadIdx.x; i < NPART; i += 32) {
            s  += part[b * NPART + i];
            ss += part[BATCH * NPART + b * NPART + i];
        }
#pragma unroll
        for (int o = 16; o; o >>= 1) {
            s  += __shfl_xor_sync(0xffffffffu, s, o);
            ss += __shfl_xor_sync(0xffffffffu, ss, o);
        }
        if (threadIdx.x == 0) {
            const float inv = 1.f / (float)PERBATCH;
            float mean = s * inv;
            s_mu = mean;
            s_rs = rsqrtf(ss * inv - mean * mean + EPSV);
        }
    }
    __syncthreads();
    const int e = idx - b * (PERBATCH / 4);
    const float4 v = in4[idx];
    const float4 ww = w4[e];
    const float4 bb = b4[e];
    const float mu = s_mu, rs = s_rs;
    float4 o;
    o.x = (v.x - mu) * rs * ww.x + bb.x;
    o.y = (v.y - mu) * rs * ww.y + bb.y;
    o.z = (v.z - mu) * rs * ww.z + bb.z;
    o.w = (v.w - mu) * rs * ww.w + bb.w;
    if (WRF32) out4[idx] = o;
    if (WRTF) {
        uint4 t;
        t.x = f2tf(o.x); t.y = f2tf(o.y); t.z = f2tf(o.z); t.w = f2tf(o.w);
        out_tf4[idx] = t;
    }
}

// ---------------------------------------------------------------------------
extern "C" void kernel_launch(void* const* d_in, const int* in_sizes, int n_in,
                              void* d_out, int out_size)
{
    const float* x    = (const float*)d_in[0];
    const float* Wq   = (const float*)d_in[1];
    const float* bq   = (const float*)d_in[2];
    const float* Wk   = (const float*)d_in[3];
    const float* bk   = (const float*)d_in[4];
    const float* Wv   = (const float*)d_in[5];
    const float* bv   = (const float*)d_in[6];
    const float* Wf   = (const float*)d_in[7];
    const float* bf   = (const float*)d_in[8];
    const float* ln1w = (const float*)d_in[9];
    const float* ln1b = (const float*)d_in[10];
    const float* ln2w = (const float*)d_in[11];
    const float* ln2b = (const float*)d_in[12];
    const float* W1   = (const float*)d_in[13];
    const float* b1   = (const float*)d_in[14];
    const float* W2   = (const float*)d_in[15];
    const float* b2   = (const float*)d_in[16];
    float* out = (float*)d_out;

    uint32_t *xc, *wq, *wkT, *wv, *wf, *w1, *w2, *qctf, *xbtf, *mgtf, *out1tf, *hidtf;
    float *u, *attent, *tbuf, *part, *wbk, *cbk;
    cudaGetSymbolAddress((void**)&xc, g_xc);
    cudaGetSymbolAddress((void**)&wq, g_wq);
    cudaGetSymbolAddress((void**)&wkT, g_wkT);
    cudaGetSymbolAddress((void**)&wv, g_wv);
    cudaGetSymbolAddress((void**)&wf, g_wf);
    cudaGetSymbolAddress((void**)&w1, g_w1);
    cudaGetSymbolAddress((void**)&w2, g_w2);
    cudaGetSymbolAddress((void**)&wbk, g_wbk);
    cudaGetSymbolAddress((void**)&cbk, g_cbk);
    cudaGetSymbolAddress((void**)&qctf, g_qctf);
    cudaGetSymbolAddress((void**)&u, g_u);
    cudaGetSymbolAddress((void**)&xbtf, g_xbtf);
    cudaGetSymbolAddress((void**)&mgtf, g_mgtf);
    cudaGetSymbolAddress((void**)&attent, g_attent);
    cudaGetSymbolAddress((void**)&out1tf, g_out1tf);
    cudaGetSymbolAddress((void**)&hidtf, g_hidtf);
    cudaGetSymbolAddress((void**)&tbuf, g_t);
    cudaGetSymbolAddress((void**)&part, g_part);

    cudaFuncSetAttribute(mm_tcw,
                         cudaFuncAttributeMaxDynamicSharedMemorySize, SMEMW);

    const int MR = SITES / BMT;  // 80

    // 0: convert operands + cterm vectors
    convert_tf<<<8200, 256>>>(Wq, Wk, Wv, Wf, W1, W2, x, bq, bk);

    // K1: qctf = tf32(xc @ Wq^T + bq)
    mm_tc<false, false, true, false, true, false><<<dim3(4, MR, 1), 128>>>(
        xc, FDIM, 0,  wq, FDIM, 0,
        nullptr, qctf, FDIM, 0,  bq, 0, nullptr, FDIM, nullptr);

    // K2: u_h = qc_h @ wkT_h^T  (fp32)
    mm_tc<false, false, false, true, false, false><<<dim3(4, MR, HHEADS), 128>>>(
        qctf, FDIM, DHEAD,  wkT, DHEAD, FDIM*DHEAD,
        u, nullptr, HHEADS*FDIM, FDIM,  nullptr, 0, nullptr, DHEAD, nullptr);

    // K3: attention -> xbar (tf32)
    attn_kernel<<<SITES, 256>>>(x, u, wbk, cbk, xbtf);

    // K4a: merged_h = xbar_h @ Wv_h^T + bv_h  (tf32)
    mm_tc<false, false, true, false, true, false><<<dim3(1, MR, HHEADS), 128>>>(
        xbtf, HHEADS*FDIM, FDIM,  wv, FDIM, DHEAD*FDIM,
        nullptr, mgtf, FDIM, DHEAD,  bv, DHEAD, nullptr, FDIM, nullptr);

    // K4b: attent = merged @ Wf^T + bf   (+ LN1 partials)
    mm_tc<false, false, true, true, false, true><<<dim3(4, MR, 1), 128>>>(
        mgtf, FDIM, 0,  wf, FDIM, 0,
        attent, nullptr, FDIM, 0,  bf, 0, nullptr, FDIM, part);

    // LN1 -> out1tf only (tf32), float4-vectorized
    ln_apply<false, true><<<TOTAL/1024, 256>>>(
        (const float4*)attent, part, (const float4*)ln1w, (const float4*)ln1b,
        nullptr, (uint4*)out1tf);

    // W1: hidden = relu(out1 @ W1^T + b1)  (128x64 tiles, 640 CTAs)
    mm_tcw<<<dim3(DFFDIM/BNT, SITES/WBM, 1), 128, SMEMW>>>(
        out1tf, FDIM,  w1, FDIM,  hidtf, DFFDIM,  b1, FDIM);

    // W2: tbuf = hidden @ W2^T + b2 + tf32(out1)   (+ LN2 partials)
    mm_tc<false, true, true, true, false, true><<<dim3(4, MR, 1), 128>>>(
        hidtf, DFFDIM, 0,  w2, DFFDIM, 0,
        tbuf, nullptr, FDIM, 0,  b2, 0, out1tf, DFFDIM, part);

    // LN2 -> final output (fp32), float4-vectorized
    ln_apply<true, false><<<TOTAL/1024, 256>>>(
        (const float4*)tbuf, part, (const float4*)ln2w, (const float4*)ln2b,
        (float4*)out, nullptr);
}

// round 16
// speedup vs baseline: 1.0027x; 1.0027x over previous
#include <cuda_runtime.h>
#include <math.h>
#include <stdint.h>

// ---------------------------------------------------------------------------
// PatchAttentionNet: B=4, N=256, O=5, K=5, F=256, H=4, D=64, DFF=1024
// R1:  algebraic refactor (center-q => no k/v projections)
// R2/3: TF32 tensor-core GEMMs, pre-converted operands, ldmatrix
// R6:  LN partial sums fused into GEMM epilogues
// R8:  qc fp32 path deleted (cterm via wbk/cbk); smem-staged attn
// R14: out1 fp32 dropped; float4 LN (168.7us best)
// R16: 32x64-tile GEMM for the four 320-CTA launches (K1/K4a/K4b/W2)
//      -> 640 CTAs each (~4.3/SM); W1 back at 64x64/1280 CTAs.
// ---------------------------------------------------------------------------

#define BATCH 4
#define NPOS 256
#define OPOS 5
#define FDIM 256
#define HHEADS 4
#define DHEAD 64
#define DFFDIM 1024
#define SITES (BATCH*NPOS*OPOS)     // 5120
#define PATCHES 25
#define PERBATCH (NPOS*OPOS*FDIM)   // 327680
#define TOTAL (BATCH*PERBATCH)      // 1310720
#define EPSV 1e-5f
#define NPART 160                   // LN partials per batch (40 rowblk x 4 colblk)

// ---- scratch (device globals; allocation-free) ----
__device__ uint32_t g_xc[SITES*FDIM];
__device__ uint32_t g_wq[FDIM*FDIM];
__device__ uint32_t g_wkT[HHEADS*FDIM*DHEAD];
__device__ uint32_t g_wv[HHEADS*DHEAD*FDIM];
__device__ uint32_t g_wf[FDIM*FDIM];
__device__ uint32_t g_w1[DFFDIM*FDIM];
__device__ uint32_t g_w2[FDIM*DFFDIM];
__device__ float    g_wbk[HHEADS*FDIM];   // Wq_h^T bk_h
__device__ float    g_cbk[HHEADS];        // bq_h . bk_h
__device__ uint32_t g_qctf[SITES*FDIM];
__device__ float    g_u[SITES*HHEADS*FDIM];
__device__ uint32_t g_xbtf[SITES*HHEADS*FDIM];
__device__ uint32_t g_mgtf[SITES*FDIM];
__device__ float    g_attent[SITES*FDIM];
__device__ uint32_t g_out1tf[SITES*FDIM];
__device__ uint32_t g_hidtf[SITES*DFFDIM];
__device__ float    g_t[SITES*FDIM];
__device__ float    g_part[2*BATCH*NPART];

__device__ __forceinline__ uint32_t f2tf(float v) {
    uint32_t r;
    asm("cvt.rna.tf32.f32 %0, %1;" : "=r"(r) : "f"(v));
    return r;
}

__device__ __forceinline__ void mma_tf32(float c[4], const uint32_t a[4],
                                         uint32_t b0, uint32_t b1) {
    asm volatile(
        "mma.sync.aligned.m16n8k8.row.col.f32.tf32.tf32.f32 "
        "{%0,%1,%2,%3},{%4,%5,%6,%7},{%8,%9},{%0,%1,%2,%3};"
        : "+f"(c[0]), "+f"(c[1]), "+f"(c[2]), "+f"(c[3])
        : "r"(a[0]), "r"(a[1]), "r"(a[2]), "r"(a[3]), "r"(b0), "r"(b1));
}

__device__ __forceinline__ void ldsm4(uint32_t r[4], uint32_t addr) {
    asm volatile("ldmatrix.sync.aligned.m8n8.x4.shared.b16 {%0,%1,%2,%3}, [%4];"
                 : "=r"(r[0]), "=r"(r[1]), "=r"(r[2]), "=r"(r[3]) : "r"(addr));
}

__device__ __forceinline__ void cpa16(uint32_t dst, const void* src) {
    asm volatile("cp.async.cg.shared.global [%0], [%1], 16;" :: "r"(dst), "l"(src));
}

// ---------------------------------------------------------------------------
// One-shot tf32 conversion + cterm precompute (wbk, cbk)
// ---------------------------------------------------------------------------
__global__ void convert_tf(const float* __restrict__ Wq, const float* __restrict__ Wk,
                           const float* __restrict__ Wv, const float* __restrict__ Wf,
                           const float* __restrict__ W1, const float* __restrict__ W2,
                           const float* __restrict__ x,
                           const float* __restrict__ bq, const float* __restrict__ bk)
{
    const int idx = blockIdx.x * 256 + threadIdx.x;
    if (idx < 65536) {
        g_wq[idx] = f2tf(Wq[idx]);
    } else if (idx < 131072) {
        const int i = idx - 65536;
        const int h = i >> 14, n = (i >> 6) & 255, k = i & 63;
        g_wkT[i] = f2tf(Wk[(h*64 + k)*256 + n]);
    } else if (idx < 196608) {
        const int i = idx - 131072;
        g_wv[i] = f2tf(Wv[i]);
    } else if (idx < 262144) {
        const int i = idx - 196608;
        g_wf[i] = f2tf(Wf[i]);
    } else if (idx < 524288) {
        const int i = idx - 262144;
        g_w1[i] = f2tf(W1[i]);
    } else if (idx < 786432) {
        const int i = idx - 524288;
        g_w2[i] = f2tf(W2[i]);
    } else if (idx < 2097152) {
        const int i = idx - 786432;
        const int s = i >> 8, f = i & 255;
        g_xc[i] = f2tf(x[(long)s*(PATCHES*FDIM) + 12*FDIM + f]);
    } else if (idx < 2098176) {
        const int i = idx - 2097152;        // wbk[h][f] = sum_d Wq[h*64+d][f]*bk[h*64+d]
        const int h = i >> 8, f = i & 255;
        float a = 0.f;
#pragma unroll 8
        for (int d = 0; d < 64; d++)
            a += Wq[(h*64 + d)*256 + f] * bk[h*64 + d];
        g_wbk[i] = a;
    } else if (idx < 2098180) {
        const int h = idx - 2098176;        // cbk[h] = bq_h . bk_h
        float a = 0.f;
#pragma unroll 8
        for (int d = 0; d < 64; d++)
            a += bq[h*64 + d] * bk[h*64 + d];
        g_cbk[h] = a;
    }
}

// ---------------------------------------------------------------------------
// 64x64x32 TF32 GEMM (used for K2 and W1 — the already-1280-CTA launches)
// ---------------------------------------------------------------------------
#define BMT 64
#define BNT 64
#define BKT 32
#define PADA 36
#define PADB 36
#define ABUF (BMT*PADA)
#define BBUF (BNT*PADB)
#define SPB  (ABUF+BBUF)

template<bool RELU, bool HASBIAS, bool WRF32, bool WRTF>
__global__ void __launch_bounds__(128)
mm_tc(const uint32_t* __restrict__ A, int lda, int sAz,
      const uint32_t* __restrict__ B, int ldb, int sBz,
      float* __restrict__ C, uint32_t* __restrict__ Ctf, int ldc, int sCz,
      const float* __restrict__ bias, int sBiasz, int K)
{
    __shared__ uint32_t sm[2*SPB];
    const int z = blockIdx.z;
    A += (long)z * sAz;
    B += (long)z * sBz;
    const long coff_z = (long)z * sCz;
    const float* biasz = HASBIAS ? bias + (long)z * sBiasz : bias;

    const int m0 = blockIdx.y * BMT;
    const int n0 = blockIdx.x * BNT;
    const int tid = threadIdx.x;
    const int warp = tid >> 5, lane = tid & 31;
    const int g = lane >> 2, tig = lane & 3;
    const int wm = warp >> 1, wn = warp & 1;

    const uint32_t uS = (uint32_t)__cvta_generic_to_shared(sm);
    const uint32_t aoff = (uint32_t)(((wm*32 + (lane & 15)) * PADA + ((lane >> 4) << 2)) * 4);
    const uint32_t boff = (uint32_t)((ABUF + (wn*32 + (lane & 15)) * PADB + ((lane >> 4) << 2)) * 4);

    float c[2][4][4];
#pragma unroll
    for (int mf = 0; mf < 2; mf++)
#pragma unroll
        for (int nf = 0; nf < 4; nf++)
#pragma unroll
            for (int i = 0; i < 4; i++) c[mf][nf][i] = 0.f;

    const int nslab = K / BKT;

    auto load_slab = [&](int ks, int buf) {
        const uint32_t base = uS + (uint32_t)(buf * SPB * 4);
        const uint32_t* Ag = A + (long)m0 * lda + ks * BKT;
        const uint32_t* Bg = B + (long)n0 * ldb + ks * BKT;
#pragma unroll
        for (int i = 0; i < 4; i++) {
            int id = tid + i * 128;
            int r = id >> 3;
            int kc4 = (id & 7) * 4;
            cpa16(base + (uint32_t)((r * PADA + kc4) * 4), Ag + (long)r * lda + kc4);
        }
#pragma unroll
        for (int i = 0; i < 4; i++) {
            int id = tid + i * 128;
            int r = id >> 3;
            int kc4 = (id & 7) * 4;
            cpa16(base + (uint32_t)((ABUF + r * PADB + kc4) * 4), Bg + (long)r * ldb + kc4);
        }
        asm volatile("cp.async.commit_group;");
    };

    load_slab(0, 0);

    for (int ks = 0; ks < nslab; ks++) {
        const int cur = ks & 1;
        if (ks + 1 < nslab) {
            load_slab(ks + 1, cur ^ 1);
            asm volatile("cp.async.wait_group 1;");
        } else {
            asm volatile("cp.async.wait_group 0;");
        }
        __syncthreads();

        const uint32_t sb = uS + (uint32_t)(cur * SPB * 4);
        const uint32_t aaddr = sb + aoff;
        const uint32_t baddr = sb + boff;

#pragma unroll
        for (int kc = 0; kc < BKT; kc += 8) {
            uint32_t a0[4], a1[4], b01[4], b23[4];
            ldsm4(a0, aaddr + kc * 4);
            ldsm4(a1, aaddr + (16 * PADA + kc) * 4);
            ldsm4(b01, baddr + kc * 4);
            ldsm4(b23, baddr + (16 * PADB + kc) * 4);
            mma_tf32(c[0][0], a0, b01[0], b01[2]);
            mma_tf32(c[0][1], a0, b01[1], b01[3]);
            mma_tf32(c[0][2], a0, b23[0], b23[2]);
            mma_tf32(c[0][3], a0, b23[1], b23[3]);
            mma_tf32(c[1][0], a1, b01[0], b01[2]);
            mma_tf32(c[1][1], a1, b01[1], b01[3]);
            mma_tf32(c[1][2], a1, b23[0], b23[2]);
            mma_tf32(c[1][3], a1, b23[1], b23[3]);
        }
        __syncthreads();
    }

#pragma unroll
    for (int mf = 0; mf < 2; mf++) {
        const int r0 = m0 + wm*32 + mf*16 + g;
#pragma unroll
        for (int nf = 0; nf < 4; nf++) {
            const int col = n0 + wn*32 + nf*8 + 2*tig;
            float bx = 0.f, by = 0.f;
            if (HASBIAS) {
                float2 bb = *(const float2*)&biasz[col];
                bx = bb.x; by = bb.y;
            }
            float v0 = c[mf][nf][0] + bx, v1 = c[mf][nf][1] + by;
            float v2 = c[mf][nf][2] + bx, v3 = c[mf][nf][3] + by;
            if (RELU) {
                v0 = fmaxf(v0, 0.f); v1 = fmaxf(v1, 0.f);
                v2 = fmaxf(v2, 0.f); v3 = fmaxf(v3, 0.f);
            }
            if (WRF32) {
                float2 o0; o0.x = v0; o0.y = v1;
                float2 o1; o1.x = v2; o1.y = v3;
                *(float2*)&C[(long)r0 * ldc + coff_z + col] = o0;
                *(float2*)&C[(long)(r0 + 8) * ldc + coff_z + col] = o1;
            }
            if (WRTF) {
                uint2 t0; t0.x = f2tf(v0); t0.y = f2tf(v1);
                uint2 t1; t1.x = f2tf(v2); t1.y = f2tf(v3);
                *(uint2*)&Ctf[(long)r0 * ldc + coff_z + col] = t0;
                *(uint2*)&Ctf[(long)(r0 + 8) * ldc + coff_z + col] = t1;
            }
        }
    }
}

// ---------------------------------------------------------------------------
// 32x64x32 TF32 GEMM (for the formerly-320-CTA launches: K1/K4a/K4b/W2).
// 128 threads, warp tile 16x32 (1 A-ldsm + 2 B-ldsm + 4 mma per k8).
// Smem 27.6KB/CTA, low regs -> 640-CTA grids fill ~4.3 CTAs/SM.
// ---------------------------------------------------------------------------
#define BM3 32
#define ABUF3 (BM3*PADA)           // 1152 u32
#define SPB3 (ABUF3+BBUF)          // 3456 u32

template<bool RELU, bool HASRES, bool HASBIAS, bool WRF32, bool WRTF, bool LNPART>
__global__ void __launch_bounds__(128)
mm_tc32(const uint32_t* __restrict__ A, int lda, int sAz,
        const uint32_t* __restrict__ B, int ldb, int sBz,
        float* __restrict__ C, uint32_t* __restrict__ Ctf, int ldc, int sCz,
        const float* __restrict__ bias, int sBiasz,
        const uint32_t* __restrict__ res, int K,
        float* __restrict__ part)
{
    __shared__ uint32_t sm[2*SPB3];
    const int z = blockIdx.z;
    A += (long)z * sAz;
    B += (long)z * sBz;
    const long coff_z = (long)z * sCz;
    const float* biasz = HASBIAS ? bias + (long)z * sBiasz : bias;

    const int m0 = blockIdx.y * BM3;
    const int n0 = blockIdx.x * BNT;
    const int tid = threadIdx.x;
    const int warp = tid >> 5, lane = tid & 31;
    const int g = lane >> 2, tig = lane & 3;
    const int wm = warp >> 1, wn = warp & 1;

    const uint32_t uS = (uint32_t)__cvta_generic_to_shared(sm);
    const uint32_t aoff = (uint32_t)(((wm*16 + (lane & 15)) * PADA + ((lane >> 4) << 2)) * 4);
    const uint32_t boff = (uint32_t)((ABUF3 + (wn*32 + (lane & 15)) * PADB + ((lane >> 4) << 2)) * 4);

    float c[4][4];
#pragma unroll
    for (int nf = 0; nf < 4; nf++)
#pragma unroll
        for (int i = 0; i < 4; i++) c[nf][i] = 0.f;

    const int nslab = K / BKT;

    auto load_slab = [&](int ks, int buf) {
        const uint32_t base = uS + (uint32_t)(buf * SPB3 * 4);
        const uint32_t* Ag = A + (long)m0 * lda + ks * BKT;
        const uint32_t* Bg = B + (long)n0 * ldb + ks * BKT;
#pragma unroll
        for (int i = 0; i < 2; i++) {          // 32 rows x 8 float4
            int id = tid + i * 128;
            int r = id >> 3;
            int kc4 = (id & 7) * 4;
            cpa16(base + (uint32_t)((r * PADA + kc4) * 4), Ag + (long)r * lda + kc4);
        }
#pragma unroll
        for (int i = 0; i < 4; i++) {          // 64 rows x 8 float4
            int id = tid + i * 128;
            int r = id >> 3;
            int kc4 = (id & 7) * 4;
            cpa16(base + (uint32_t)((ABUF3 + r * PADB + kc4) * 4), Bg + (long)r * ldb + kc4);
        }
        asm volatile("cp.async.commit_group;");
    };

    load_slab(0, 0);

    for (int ks = 0; ks < nslab; ks++) {
        const int cur = ks & 1;
        if (ks + 1 < nslab) {
            load_slab(ks + 1, cur ^ 1);
            asm volatile("cp.async.wait_group 1;");
        } else {
            asm volatile("cp.async.wait_group 0;");
        }
        __syncthreads();

        const uint32_t sb = uS + (uint32_t)(cur * SPB3 * 4);
        const uint32_t aaddr = sb + aoff;
        const uint32_t baddr = sb + boff;

#pragma unroll
        for (int kc = 0; kc < BKT; kc += 8) {
            uint32_t a0[4], b01[4], b23[4];
            ldsm4(a0, aaddr + kc * 4);
            ldsm4(b01, baddr + kc * 4);
            ldsm4(b23, baddr + (16 * PADB + kc) * 4);
            mma_tf32(c[0], a0, b01[0], b01[2]);
            mma_tf32(c[1], a0, b01[1], b01[3]);
            mma_tf32(c[2], a0, b23[0], b23[2]);
            mma_tf32(c[3], a0, b23[1], b23[3]);
        }
        __syncthreads();
    }

    float ls = 0.f, lss = 0.f;
    {
        const int r0 = m0 + wm*16 + g;
#pragma unroll
        for (int nf = 0; nf < 4; nf++) {
            const int col = n0 + wn*32 + nf*8 + 2*tig;
            float bx = 0.f, by = 0.f;
            if (HASBIAS) {
                float2 bb = *(const float2*)&biasz[col];
                bx = bb.x; by = bb.y;
            }
            float v0 = c[nf][0] + bx, v1 = c[nf][1] + by;
            float v2 = c[nf][2] + bx, v3 = c[nf][3] + by;
            if (RELU) {
                v0 = fmaxf(v0, 0.f); v1 = fmaxf(v1, 0.f);
                v2 = fmaxf(v2, 0.f); v3 = fmaxf(v3, 0.f);
            }
            if (HASRES) {   // residual stored as tf32 bits
                uint2 ra = *(const uint2*)&res[(long)r0 * ldc + coff_z + col];
                uint2 rb = *(const uint2*)&res[(long)(r0 + 8) * ldc + coff_z + col];
                v0 += __uint_as_float(ra.x); v1 += __uint_as_float(ra.y);
                v2 += __uint_as_float(rb.x); v3 += __uint_as_float(rb.y);
            }
            if (LNPART) {
                ls  += (v0 + v1) + (v2 + v3);
                lss += (v0*v0 + v1*v1) + (v2*v2 + v3*v3);
            }
            if (WRF32) {
                float2 o0; o0.x = v0; o0.y = v1;
                float2 o1; o1.x = v2; o1.y = v3;
                *(float2*)&C[(long)r0 * ldc + coff_z + col] = o0;
                *(float2*)&C[(long)(r0 + 8) * ldc + coff_z + col] = o1;
            }
            if (WRTF) {
                uint2 t0; t0.x = f2tf(v0); t0.y = f2tf(v1);
                uint2 t1; t1.x = f2tf(v2); t1.y = f2tf(v3);
                *(uint2*)&Ctf[(long)r0 * ldc + coff_z + col] = t0;
                *(uint2*)&Ctf[(long)(r0 + 8) * ldc + coff_z + col] = t1;
            }
        }
    }

    if (LNPART) {
        __shared__ float red[2][4];
#pragma unroll
        for (int o = 16; o; o >>= 1) {
            ls  += __shfl_xor_sync(0xffffffffu, ls, o);
            lss += __shfl_xor_sync(0xffffffffu, lss, o);
        }
        if (lane == 0) { red[0][warp] = ls; red[1][warp] = lss; }
        __syncthreads();
        if (tid == 0) {
            float S = (red[0][0] + red[0][1]) + (red[0][2] + red[0][3]);
            float SS = (red[1][0] + red[1][1]) + (red[1][2] + red[1][3]);
            const int b = blockIdx.y / 40;
            const int idx = b * NPART + (blockIdx.y % 40) * 4 + blockIdx.x;
            part[idx] = S;
            part[BATCH*NPART + idx] = SS;
        }
    }
}

// ---------------------------------------------------------------------------
// Attention: smem-staged X/u, cterm from sX[12].wbk + cbk. (measured optimum)
// ---------------------------------------------------------------------------
__global__ void __launch_bounds__(256) attn_kernel(
    const float* __restrict__ x,
    const float* __restrict__ u,
    const float* __restrict__ wbk, const float* __restrict__ cbk,
    uint32_t* __restrict__ xbar_tf)
{
    __shared__ float sX[PATCHES * FDIM];
    __shared__ float sU[HHEADS * FDIM];
    __shared__ float sct[HHEADS];
    __shared__ float sSc[HHEADS * PATCHES];
    __shared__ float sWp[PATCHES * 4];

    const int s = blockIdx.x;
    const int tid = threadIdx.x;
    const int warp = tid >> 5, lane = tid & 31;

    const uint32_t uX = (uint32_t)__cvta_generic_to_shared(sX);
    const uint32_t uU = (uint32_t)__cvta_generic_to_shared(sU);
    const float* xg = x + (long)s * (PATCHES * FDIM);
    for (int i = tid; i < PATCHES * FDIM / 4; i += 256)
        cpa16(uX + (uint32_t)i * 16, xg + i * 4);
    cpa16(uU + (uint32_t)tid * 16, u + (long)s * (HHEADS * FDIM) + tid * 4);
    asm volatile("cp.async.commit_group;");
    asm volatile("cp.async.wait_group 0;");
    __syncthreads();

    if (warp < HHEADS) {
        float v = 0.f;
#pragma unroll
        for (int j = 0; j < 8; j++)
            v += sX[12*FDIM + lane + 32*j] * wbk[warp*FDIM + lane + 32*j];
#pragma unroll
        for (int o = 16; o; o >>= 1) v += __shfl_xor_sync(0xffffffffu, v, o);
        if (lane == 0) sct[warp] = v + cbk[warp];
    }

    float4 ua[HHEADS], ub[HHEADS];
#pragma unroll
    for (int h = 0; h < HHEADS; h++) {
        ua[h] = ((const float4*)&sU[h * FDIM])[lane];
        ub[h] = ((const float4*)&sU[h * FDIM])[lane + 32];
    }
    __syncthreads();

    for (int p = warp; p < PATCHES; p += 8) {
        const float4 xa = ((const float4*)&sX[p * FDIM])[lane];
        const float4 xb = ((const float4*)&sX[p * FDIM])[lane + 32];
        float acc[HHEADS];
#pragma unroll
        for (int h = 0; h < HHEADS; h++) {
            acc[h] = xa.x*ua[h].x + xa.y*ua[h].y + xa.z*ua[h].z + xa.w*ua[h].w
                   + xb.x*ub[h].x + xb.y*ub[h].y + xb.z*ub[h].z + xb.w*ub[h].w;
        }
#pragma unroll
        for (int o = 16; o; o >>= 1) {
#pragma unroll
            for (int h = 0; h < HHEADS; h++)
                acc[h] += __shfl_xor_sync(0xffffffffu, acc[h], o);
        }
        if (lane == 0) {
#pragma unroll
            for (int h = 0; h < HHEADS; h++)
                sSc[h * PATCHES + p] = (acc[h] + sct[h]) * 0.125f;
        }
    }
    __syncthreads();

    if (warp < HHEADS) {
        float v = (lane < PATCHES) ? sSc[warp * PATCHES + lane] : -1e30f;
        float m = v;
#pragma unroll
        for (int o = 16; o; o >>= 1) m = fmaxf(m, __shfl_xor_sync(0xffffffffu, m, o));
        float e = (lane < PATCHES) ? __expf(v - m) : 0.f;
        float sum = e;
#pragma unroll
        for (int o = 16; o; o >>= 1) sum += __shfl_xor_sync(0xffffffffu, sum, o);
        if (lane < PATCHES) sWp[lane * 4 + warp] = e / sum;
    }
    __syncthreads();

    float acc0 = 0.f, acc1 = 0.f, acc2 = 0.f, acc3 = 0.f;
#pragma unroll
    for (int p = 0; p < PATCHES; p++) {
        const float xv = sX[p * FDIM + tid];
        const float4 wv = *(const float4*)&sWp[p * 4];
        acc0 += wv.x * xv; acc1 += wv.y * xv;
        acc2 += wv.z * xv; acc3 += wv.w * xv;
    }
    uint32_t* xo = xbar_tf + (long)s * (HHEADS * FDIM) + tid;
    xo[0*FDIM] = f2tf(acc0);
    xo[1*FDIM] = f2tf(acc1);
    xo[2*FDIM] = f2tf(acc2);
    xo[3*FDIM] = f2tf(acc3);
}

// ---------------------------------------------------------------------------
// LN apply (float4-vectorized)
// ---------------------------------------------------------------------------
template<bool WRF32, bool WRTF>
__global__ void ln_apply(const float4* __restrict__ in4, const float* __restrict__ part,
                         const float4* __restrict__ w4, const float4* __restrict__ b4,
                         float4* __restrict__ out4, uint4* __restrict__ out_tf4)
{
    __shared__ float s_mu, s_rs;
    const int idx = blockIdx.x * 256 + threadIdx.x;
    const int b = blockIdx.x / (PERBATCH / 1024);
    if (threadIdx.x < 32) {
        float s = 0.f, ss = 0.f;
        for (int i = threadIdx.x; i < NPART; i += 32) {
            s  += part[b * NPART + i];
            ss += part[BATCH * NPART + b * NPART + i];
        }
#pragma unroll
        for (int o = 16; o; o >>= 1) {
            s  += __shfl_xor_sync(0xffffffffu, s, o);
            ss += __shfl_xor_sync(0xffffffffu, ss, o);
        }
        if (threadIdx.x == 0) {
            const float inv = 1.f / (float)PERBATCH;
            float mean = s * inv;
            s_mu = mean;
            s_rs = rsqrtf(ss * inv - mean * mean + EPSV);
        }
    }
    __syncthreads();
    const int e = idx - b * (PERBATCH / 4);
    const float4 v = in4[idx];
    const float4 ww = w4[e];
    const float4 bb = b4[e];
    const float mu = s_mu, rs = s_rs;
    float4 o;
    o.x = (v.x - mu) * rs * ww.x + bb.x;
    o.y = (v.y - mu) * rs * ww.y + bb.y;
    o.z = (v.z - mu) * rs * ww.z + bb.z;
    o.w = (v.w - mu) * rs * ww.w + bb.w;
    if (WRF32) out4[idx] = o;
    if (WRTF) {
        uint4 t;
        t.x = f2tf(o.x); t.y = f2tf(o.y); t.z = f2tf(o.z); t.w = f2tf(o.w);
        out_tf4[idx] = t;
    }
}

// ---------------------------------------------------------------------------
extern "C" void kernel_launch(void* const* d_in, const int* in_sizes, int n_in,
                              void* d_out, int out_size)
{
    const float* x    = (const float*)d_in[0];
    const float* Wq   = (const float*)d_in[1];
    const float* bq   = (const float*)d_in[2];
    const float* Wk   = (const float*)d_in[3];
    const float* bk   = (const float*)d_in[4];
    const float* Wv   = (const float*)d_in[5];
    const float* bv   = (const float*)d_in[6];
    const float* Wf   = (const float*)d_in[7];
    const float* bf   = (const float*)d_in[8];
    const float* ln1w = (const float*)d_in[9];
    const float* ln1b = (const float*)d_in[10];
    const float* ln2w = (const float*)d_in[11];
    const float* ln2b = (const float*)d_in[12];
    const float* W1   = (const float*)d_in[13];
    const float* b1   = (const float*)d_in[14];
    const float* W2   = (const float*)d_in[15];
    const float* b2   = (const float*)d_in[16];
    float* out = (float*)d_out;

    uint32_t *xc, *wq, *wkT, *wv, *wf, *w1, *w2, *qctf, *xbtf, *mgtf, *out1tf, *hidtf;
    float *u, *attent, *tbuf, *part, *wbk, *cbk;
    cudaGetSymbolAddress((void**)&xc, g_xc);
    cudaGetSymbolAddress((void**)&wq, g_wq);
    cudaGetSymbolAddress((void**)&wkT, g_wkT);
    cudaGetSymbolAddress((void**)&wv, g_wv);
    cudaGetSymbolAddress((void**)&wf, g_wf);
    cudaGetSymbolAddress((void**)&w1, g_w1);
    cudaGetSymbolAddress((void**)&w2, g_w2);
    cudaGetSymbolAddress((void**)&wbk, g_wbk);
    cudaGetSymbolAddress((void**)&cbk, g_cbk);
    cudaGetSymbolAddress((void**)&qctf, g_qctf);
    cudaGetSymbolAddress((void**)&u, g_u);
    cudaGetSymbolAddress((void**)&xbtf, g_xbtf);
    cudaGetSymbolAddress((void**)&mgtf, g_mgtf);
    cudaGetSymbolAddress((void**)&attent, g_attent);
    cudaGetSymbolAddress((void**)&out1tf, g_out1tf);
    cudaGetSymbolAddress((void**)&hidtf, g_hidtf);
    cudaGetSymbolAddress((void**)&tbuf, g_t);
    cudaGetSymbolAddress((void**)&part, g_part);

    const int MR = SITES / BMT;   // 80
    const int MR3 = SITES / BM3;  // 160

    // 0: convert operands + cterm vectors
    convert_tf<<<8200, 256>>>(Wq, Wk, Wv, Wf, W1, W2, x, bq, bk);

    // K1: qctf = tf32(xc @ Wq^T + bq)   (32x64 tiles, 640 CTAs)
    mm_tc32<false, false, true, false, true, false><<<dim3(4, MR3, 1), 128>>>(
        xc, FDIM, 0,  wq, FDIM, 0,
        nullptr, qctf, FDIM, 0,  bq, 0, nullptr, FDIM, nullptr);

    // K2: u_h = qc_h @ wkT_h^T  (fp32; 64x64, 1280 CTAs)
    mm_tc<false, false, true, false><<<dim3(4, MR, HHEADS), 128>>>(
        qctf, FDIM, DHEAD,  wkT, DHEAD, FDIM*DHEAD,
        u, nullptr, HHEADS*FDIM, FDIM,  nullptr, 0, DHEAD);

    // K3: attention -> xbar (tf32)
    attn_kernel<<<SITES, 256>>>(x, u, wbk, cbk, xbtf);

    // K4a: merged_h = xbar_h @ Wv_h^T + bv_h  (tf32; 32x64, 640 CTAs)
    mm_tc32<false, false, true, false, true, false><<<dim3(1, MR3, HHEADS), 128>>>(
        xbtf, HHEADS*FDIM, FDIM,  wv, FDIM, DHEAD*FDIM,
        nullptr, mgtf, FDIM, DHEAD,  bv, DHEAD, nullptr, FDIM, nullptr);

    // K4b: attent = merged @ Wf^T + bf (+ LN1 partials; 32x64, 640 CTAs)
    mm_tc32<false, false, true, true, false, true><<<dim3(4, MR3, 1), 128>>>(
        mgtf, FDIM, 0,  wf, FDIM, 0,
        attent, nullptr, FDIM, 0,  bf, 0, nullptr, FDIM, part);

    // LN1 -> out1tf only (tf32), float4-vectorized
    ln_apply<false, true><<<TOTAL/1024, 256>>>(
        (const float4*)attent, part, (const float4*)ln1w, (const float4*)ln1b,
        nullptr, (uint4*)out1tf);

    // W1: hidden = relu(out1 @ W1^T + b1)  (64x64, 1280 CTAs)
    mm_tc<true, true, false, true><<<dim3(DFFDIM/BNT, MR, 1), 128>>>(
        out1tf, FDIM, 0,  w1, FDIM, 0,
        nullptr, hidtf, DFFDIM, 0,  b1, 0, FDIM);

    // W2: tbuf = hidden @ W2^T + b2 + tf32(out1) (+ LN2 partials; 32x64, 640)
    mm_tc32<false, true, true, true, false, true><<<dim3(4, MR3, 1), 128>>>(
        hidtf, DFFDIM, 0,  w2, DFFDIM, 0,
        tbuf, nullptr, FDIM, 0,  b2, 0, out1tf, DFFDIM, part);

    // LN2 -> final output (fp32), float4-vectorized
    ln_apply<true, false><<<TOTAL/1024, 256>>>(
        (const float4*)tbuf, part, (const float4*)ln2w, (const float4*)ln2b,
        (float4*)out, nullptr);
}